// round 1
// baseline (speedup 1.0000x reference)
#include <cuda_runtime.h>
#include <cuda_bf16.h>

// EMA: y[n] = w*x[n] + (1-w)*y[n-1], scan over last (contiguous) axis.
// Shapes: input (16,8,256,2048) f32, initial_state (16,8,256), weight (8,256).
// One warp per series (32768 series). Each lane holds float4 -> 128 elems per
// warp iteration, 16 iterations. Affine warp scan resolves the recurrence.

#define N_FRAMES 2048
#define SERIES_PER_WB 2048   /* N_RES * N_BINS = 8*256 */
#define N_SERIES 32768       /* 16*8*256 */

__global__ __launch_bounds__(256)
void ema_scan_kernel(const float* __restrict__ x,
                     const float* __restrict__ init_state,
                     const float* __restrict__ weight,
                     float* __restrict__ y) {
    const int warp_global = (blockIdx.x * blockDim.x + threadIdx.x) >> 5;
    const int lane = threadIdx.x & 31;
    if (warp_global >= N_SERIES) return;

    const int series = warp_global;

    // weight index = series % (N_RES*N_BINS); clamp to [0,1]
    const float w_raw = weight[series & (SERIES_PER_WB - 1)];
    const float w   = fminf(fmaxf(w_raw, 0.0f), 1.0f);
    const float omw = 1.0f - w;
    const float omw2 = omw * omw;
    const float omw4 = omw2 * omw2;

    float carry = init_state[series];

    const float4* __restrict__ xin  =
        reinterpret_cast<const float4*>(x + (size_t)series * N_FRAMES);
    float4* __restrict__ yout =
        reinterpret_cast<float4*>(y + (size_t)series * N_FRAMES);

    #pragma unroll 4
    for (int it = 0; it < N_FRAMES / 128; ++it) {
        float4 v = xin[it * 32 + lane];

        // Local composite over this lane's 4 elements:
        // map is y -> omw^4 * y + B, where B is the EMA of the 4 x's from 0.
        float b = w * v.x;
        b = fmaf(omw, b, w * v.y);
        b = fmaf(omw, b, w * v.z);
        b = fmaf(omw, b, w * v.w);

        float A = omw4;
        float B = b;

        // Inclusive Hillis-Steele scan of affine maps across lanes.
        // Compose (A,B) with the segment ending d lanes earlier:
        // (A,B) <- (A*A_up, A*B_up + B)
        #pragma unroll
        for (int d = 1; d < 32; d <<= 1) {
            float A_up = __shfl_up_sync(0xFFFFFFFFu, A, d);
            float B_up = __shfl_up_sync(0xFFFFFFFFu, B, d);
            if (lane >= d) {
                B = fmaf(A, B_up, B);
                A *= A_up;
            }
        }

        // Exclusive prefix -> incoming state for this lane.
        float Ae = __shfl_up_sync(0xFFFFFFFFu, A, 1);
        float Be = __shfl_up_sync(0xFFFFFFFFu, B, 1);
        float y_in = (lane == 0) ? carry : fmaf(Ae, carry, Be);

        // Reproduce the exact sequential per-element recurrence locally.
        float y0 = fmaf(omw, y_in, w * v.x);
        float y1 = fmaf(omw, y0,  w * v.y);
        float y2 = fmaf(omw, y1,  w * v.z);
        float y3 = fmaf(omw, y2,  w * v.w);

        yout[it * 32 + lane] = make_float4(y0, y1, y2, y3);

        // Carry = lane 31's final value (== A31*carry + B31).
        carry = __shfl_sync(0xFFFFFFFFu, y3, 31);
    }
}

extern "C" void kernel_launch(void* const* d_in, const int* in_sizes, int n_in,
                              void* d_out, int out_size) {
    const float* x    = (const float*)d_in[0];   // input (16,8,256,2048)
    const float* init = (const float*)d_in[1];   // initial_state (16,8,256)
    const float* wgt  = (const float*)d_in[2];   // weight (8,256)
    float* y = (float*)d_out;

    // 32768 warps, 8 warps (256 threads) per block -> 4096 blocks.
    const int threads = 256;
    const int blocks = (N_SERIES * 32) / threads;
    ema_scan_kernel<<<blocks, threads>>>(x, init, wgt, y);
}